// round 4
// baseline (speedup 1.0000x reference)
#include <cuda_runtime.h>
#include <stdint.h>

// diag(A) @ B : out[i][j] = A[i] * B[i][j]
// N = 8192 rows, M = 8192 cols, fp32. Pure HBM-streaming kernel.
//
// R3: persistent single-wave grid (148 SMs x 8 blocks, 256 thr, <=32 regs)
// to kill wave-transition overhead and tail spread. Each grid-stride step
// handles 4 contiguous-per-thread float4 (MLP_p1=4), streaming hints.

#define THREADS 256
#define UNROLL  4
#define NSM     148
#define BLKS_PER_SM 8

__global__ void __launch_bounds__(THREADS, BLKS_PER_SM) diag_scale_persist(
    const float* __restrict__ A,
    const float4* __restrict__ B4,
    float4* __restrict__ out4,
    long long n_vec)   // N*M/4 float4 total
{
    const int vecs_per_row_log2 = 11;  // M/4 = 2048 float4 per row

    // Each block processes chunks of THREADS*UNROLL float4 (16 KB span).
    const long long chunk = (long long)THREADS * UNROLL;
    long long v0 = (long long)blockIdx.x * chunk + threadIdx.x;
    const long long gstride = (long long)gridDim.x * chunk;

    for (; v0 < n_vec; v0 += gstride) {
        // Front-batch 4 independent LDG.128
        float4 b[UNROLL];
        int row[UNROLL];
#pragma unroll
        for (int k = 0; k < UNROLL; k++) {
            long long v = v0 + (long long)k * THREADS;
            row[k] = (int)(v >> vecs_per_row_log2);
            b[k] = __ldcs(&B4[v]);
        }
#pragma unroll
        for (int k = 0; k < UNROLL; k++) {
            float a = __ldg(&A[row[k]]);
            float4 o;
            o.x = a * b[k].x;
            o.y = a * b[k].y;
            o.z = a * b[k].z;
            o.w = a * b[k].w;
            __stcs(&out4[v0 + (long long)k * THREADS], o);
        }
    }
}

extern "C" void kernel_launch(void* const* d_in, const int* in_sizes, int n_in,
                              void* d_out, int out_size)
{
    const float* A = (const float*)d_in[0];
    const float4* B4 = (const float4*)d_in[1];
    float4* out4 = (float4*)d_out;

    long long n_vec = (long long)out_size >> 2;  // 16777216 float4

    int blocks = NSM * BLKS_PER_SM;  // 1184 — exactly one wave
    diag_scale_persist<<<blocks, THREADS>>>(A, B4, out4, n_vec);
}

// round 5
// speedup vs baseline: 1.1300x; 1.1300x over previous
#include <cuda_runtime.h>
#include <stdint.h>

// diag(A) @ B : out[i][j] = A[i] * B[i][j]
// N = 8192 rows, M = 8192 cols, fp32. Pure HBM-streaming kernel.
//
// R4: one block == one row, 512 threads x 4 float4 (= 8192 floats = M).
// Front-batched loads (MLP_p1=4), streaming cache hints, <=32 regs for
// full occupancy, flat 8192-block grid (HW scheduler overlaps waves).

#define THREADS 512
#define UNROLL  4   // 512 * 4 * 4 floats = 8192 = M (one row per block)

__global__ void __launch_bounds__(THREADS) diag_scale_row512(
    const float* __restrict__ A,
    const float4* __restrict__ B4,
    float4* __restrict__ out4)
{
    const int row = blockIdx.x;                 // 8192 blocks = 8192 rows
    const float a = __ldg(&A[row]);

    const long long base = (long long)row * (THREADS * UNROLL) + threadIdx.x;

    // Front-batch all loads: 4 independent LDG.128 in flight per thread.
    float4 b[UNROLL];
#pragma unroll
    for (int k = 0; k < UNROLL; k++) {
        b[k] = __ldcs(&B4[base + (long long)k * THREADS]);
    }

#pragma unroll
    for (int k = 0; k < UNROLL; k++) {
        float4 o;
        o.x = a * b[k].x;
        o.y = a * b[k].y;
        o.z = a * b[k].z;
        o.w = a * b[k].w;
        __stcs(&out4[base + (long long)k * THREADS], o);
    }
}

extern "C" void kernel_launch(void* const* d_in, const int* in_sizes, int n_in,
                              void* d_out, int out_size)
{
    const float* A = (const float*)d_in[0];
    const float4* B4 = (const float4*)d_in[1];
    float4* out4 = (float4*)d_out;

    int n_rows = (int)((long long)out_size / 8192);  // 8192

    diag_scale_row512<<<n_rows, THREADS>>>(A, B4, out4);
}